// round 14
// baseline (speedup 1.0000x reference)
#include <cuda_runtime.h>

// Shapes fixed by the problem: L=4096, B=8, D=1024, N=16
#define L_      4096
#define B_      8
#define D_      1024
#define N_      16
#define CHUNK   128
#define NCHUNK  (L_ / CHUNK)      // 32
#define BD      (B_ * D_)         // 8192
#define DN      (D_ * N_)         // 16384
#define BDN     (B_ * DN)         // 131072
#define U       8                 // prefetch depth (MLP)

// Scratch (device-global arrays: the sanctioned no-alloc workaround)
__device__ float g_q [DN];                    // q[d,n]
__device__ float g_c [DN];                    // c[d,n] = sig(damp)*ema*proj*scaling
__device__ float g_qC[DN];                    // q^CHUNK
__device__ float g_state[NCHUNK * BDN];       // 16 MB chunk states / carry-ins

typedef unsigned long long u64;

__device__ __forceinline__ u64 fma2(u64 a, u64 b, u64 c) {
    u64 d;
    asm("fma.rn.f32x2 %0, %1, %2, %3;" : "=l"(d) : "l"(a), "l"(b), "l"(c));
    return d;
}
__device__ __forceinline__ u64 add2(u64 a, u64 b) {
    u64 d;
    asm("add.rn.f32x2 %0, %1, %2;" : "=l"(d) : "l"(a), "l"(b));
    return d;
}
__device__ __forceinline__ u64 pack2(float a, float b) {
    u64 r;
    asm("mov.b64 %0, {%1, %2};" : "=l"(r) : "f"(a), "f"(b));
    return r;
}
__device__ __forceinline__ void unpack2(u64 v, float& a, float& b) {
    asm("mov.b64 {%0, %1}, %2;" : "=f"(a), "=f"(b) : "l"(v));
}

// ---------------------------------------------------------------------------
// Kernel P: per-(d,n) parameter precompute
// ---------------------------------------------------------------------------
__global__ void param_kernel(const float* __restrict__ damp,
                             const float* __restrict__ decay,
                             const float* __restrict__ ema,
                             const float* __restrict__ proj) {
    int i = blockIdx.x * blockDim.x + threadIdx.x;
    if (i >= DN) return;
    float p  = 1.0f / (1.0f + expf(-damp[i]));
    float sd = 1.0f / (1.0f + expf(-decay[i]));
    float q  = 1.0f - p * sd;                    // q in (0,1)
    g_q[i] = q;
    g_c[i] = p * ema[i] * proj[i] * 0.25f;       // scaling = (1/16)^0.5
    float qc = q;                                 // q^128 via 7 squarings
    #pragma unroll
    for (int k = 0; k < 7; k++) qc *= qc;
    g_qC[i] = qc;
}

// ---------------------------------------------------------------------------
// Kernel A: zero-init local recurrence per chunk -> end states to g_state
// grid: (D/256, NCHUNK, B), block: 256 (one thread per d)
// Double-buffered prefetch of U=8 x values keeps MLP=8 per thread.
// ---------------------------------------------------------------------------
__global__ __launch_bounds__(256) void scanA(const float* __restrict__ x) {
    const int d = blockIdx.x * 256 + threadIdx.x;
    const int j = blockIdx.y;
    const int b = blockIdx.z;

    const u64* q2 = reinterpret_cast<const u64*>(g_q) + d * 8;
    u64 q[8], s[8];
    #pragma unroll
    for (int k = 0; k < 8; k++) { q[k] = q2[k]; s[k] = 0ull; }

    const float* p = x + (j * CHUNK) * BD + b * D_ + d;
    float xb[U];
    #pragma unroll
    for (int k = 0; k < U; k++) xb[k] = __ldg(p + k * BD);
    p += U * BD;

    #pragma unroll 1
    for (int i = 0; i < CHUNK / U - 1; i++) {
        float xn[U];
        #pragma unroll
        for (int k = 0; k < U; k++) xn[k] = __ldg(p + k * BD);   // next tile in flight
        p += U * BD;
        #pragma unroll
        for (int t = 0; t < U; t++) {
            u64 x2 = pack2(xb[t], xb[t]);
            #pragma unroll
            for (int k = 0; k < 8; k++) s[k] = fma2(q[k], s[k], x2);
        }
        #pragma unroll
        for (int k = 0; k < U; k++) xb[k] = xn[k];
    }
    // final tile (no further prefetch)
    #pragma unroll
    for (int t = 0; t < U; t++) {
        u64 x2 = pack2(xb[t], xb[t]);
        #pragma unroll
        for (int k = 0; k < 8; k++) s[k] = fma2(q[k], s[k], x2);
    }

    u64* st = reinterpret_cast<u64*>(g_state)
            + (unsigned)j * (BDN / 2) + (unsigned)b * (DN / 2) + d * 8;
    #pragma unroll
    for (int k = 0; k < 8; k++) st[k] = s[k];
}

// ---------------------------------------------------------------------------
// Kernel B: sequential scan across the 32 chunks per (b,d,n), in place:
// g_state[j] becomes the CARRY-IN state for chunk j.
// ---------------------------------------------------------------------------
__global__ void scanB() {
    int t = blockIdx.x * blockDim.x + threadIdx.x;   // 0..BDN-1
    float qc = g_qC[t & (DN - 1)];
    float carry = 0.0f;
    #pragma unroll
    for (int j = 0; j < NCHUNK; j++) {
        float e = g_state[j * BDN + t];
        g_state[j * BDN + t] = carry;                // carry-in for chunk j
        carry = fmaf(qc, carry, e);                  // state after chunk j
    }
}

// ---------------------------------------------------------------------------
// Kernel C: full recurrence from carry-in + projection + residual + ReLU
// grid: (D/256, NCHUNK, B), block: 256. Same U=8 prefetch pipeline.
// ---------------------------------------------------------------------------
__global__ __launch_bounds__(256) void scanC(const float* __restrict__ x,
                                             const float* __restrict__ rw,
                                             float* __restrict__ out) {
    const int d = blockIdx.x * 256 + threadIdx.x;
    const int j = blockIdx.y;
    const int b = blockIdx.z;

    const u64* q2 = reinterpret_cast<const u64*>(g_q) + d * 8;
    const u64* c2 = reinterpret_cast<const u64*>(g_c) + d * 8;
    const u64* st = reinterpret_cast<const u64*>(g_state)
                  + (unsigned)j * (BDN / 2) + (unsigned)b * (DN / 2) + d * 8;

    u64 q[8], c[8], s[8];
    #pragma unroll
    for (int k = 0; k < 8; k++) { q[k] = q2[k]; c[k] = c2[k]; s[k] = st[k]; }
    const float w = __ldg(rw + d);

    const int base0 = (j * CHUNK) * BD + b * D_ + d;
    const float* p = x + base0;
    float*       o = out + base0;

    float xb[U];
    #pragma unroll
    for (int k = 0; k < U; k++) xb[k] = __ldg(p + k * BD);
    p += U * BD;

    #pragma unroll 1
    for (int i = 0; i < CHUNK / U; i++) {
        float xn[U];
        if (i < CHUNK / U - 1) {
            #pragma unroll
            for (int k = 0; k < U; k++) xn[k] = __ldg(p + k * BD);  // next tile in flight
            p += U * BD;
        }
        #pragma unroll
        for (int t = 0; t < U; t++) {
            float xv = xb[t];
            u64 x2 = pack2(xv, xv);
            // state update: 8 independent fma2 chains
            #pragma unroll
            for (int k = 0; k < 8; k++) s[k] = fma2(q[k], s[k], x2);
            // projection reduce: 2 accumulators
            u64 a0 = 0ull, a1 = 0ull;
            #pragma unroll
            for (int k = 0; k < 4; k++) {
                a0 = fma2(c[k],     s[k],     a0);
                a1 = fma2(c[k + 4], s[k + 4], a1);
            }
            u64 a = add2(a0, a1);
            float lo, hi;
            unpack2(a, lo, hi);
            float r = fmaf(w, xv, lo + hi);          // + residual
            o[t * BD] = fmaxf(r, 0.0f);              // ReLU
        }
        o += U * BD;
        if (i < CHUNK / U - 1) {
            #pragma unroll
            for (int k = 0; k < U; k++) xb[k] = xn[k];
        }
    }
}

// ---------------------------------------------------------------------------
extern "C" void kernel_launch(void* const* d_in, const int* in_sizes, int n_in,
                              void* d_out, int out_size) {
    const float* x    = (const float*)d_in[0];  // (L,B,D)
    const float* damp = (const float*)d_in[1];  // (D,N,1)
    const float* dec  = (const float*)d_in[2];  // (D,N,1)
    const float* ema  = (const float*)d_in[3];  // (D,N,1)
    const float* proj = (const float*)d_in[4];  // (D,N)
    const float* rw   = (const float*)d_in[5];  // (D,)
    float* out = (float*)d_out;                 // (L,B,D)

    param_kernel<<<DN / 256, 256>>>(damp, dec, ema, proj);
    scanA<<<dim3(D_ / 256, NCHUNK, B_), 256>>>(x);
    scanB<<<BDN / 256, 256>>>();
    scanC<<<dim3(D_ / 256, NCHUNK, B_), 256>>>(x, rw, out);
}

// round 15
// speedup vs baseline: 1.0042x; 1.0042x over previous
#include <cuda_runtime.h>

// Shapes fixed by the problem: L=4096, B=8, D=1024, N=16
#define L_      4096
#define B_      8
#define D_      1024
#define N_      16
#define CHUNK   128
#define NCHUNK  (L_ / CHUNK)      // 32
#define BD      (B_ * D_)         // 8192
#define DN      (D_ * N_)         // 16384
#define BDN     (B_ * DN)         // 131072
#define U       8                 // prefetch depth (MLP)

// Scratch (device-global arrays: the sanctioned no-alloc workaround)
__device__ float g_q [DN];                    // q[d,n]
__device__ float g_c [DN];                    // c[d,n] = sig(damp)*ema*proj*scaling
__device__ float g_qC[DN];                    // q^CHUNK
__device__ float g_state[NCHUNK * BDN];       // 16 MB chunk states / carry-ins

typedef unsigned long long u64;

__device__ __forceinline__ u64 fma2(u64 a, u64 b, u64 c) {
    u64 d;
    asm("fma.rn.f32x2 %0, %1, %2, %3;" : "=l"(d) : "l"(a), "l"(b), "l"(c));
    return d;
}
__device__ __forceinline__ u64 add2(u64 a, u64 b) {
    u64 d;
    asm("add.rn.f32x2 %0, %1, %2;" : "=l"(d) : "l"(a), "l"(b));
    return d;
}
__device__ __forceinline__ u64 pack2(float a, float b) {
    u64 r;
    asm("mov.b64 %0, {%1, %2};" : "=l"(r) : "f"(a), "f"(b));
    return r;
}
__device__ __forceinline__ void unpack2(u64 v, float& a, float& b) {
    asm("mov.b64 {%0, %1}, %2;" : "=f"(a), "=f"(b) : "l"(v));
}

// ---------------------------------------------------------------------------
// Kernel P: per-(d,n) parameter precompute
// ---------------------------------------------------------------------------
__global__ void param_kernel(const float* __restrict__ damp,
                             const float* __restrict__ decay,
                             const float* __restrict__ ema,
                             const float* __restrict__ proj) {
    int i = blockIdx.x * blockDim.x + threadIdx.x;
    if (i >= DN) return;
    float p  = 1.0f / (1.0f + expf(-damp[i]));
    float sd = 1.0f / (1.0f + expf(-decay[i]));
    float q  = 1.0f - p * sd;                    // q in (0,1)
    g_q[i] = q;
    g_c[i] = p * ema[i] * proj[i] * 0.25f;       // scaling = (1/16)^0.5
    float qc = q;                                 // q^128 via 7 squarings
    #pragma unroll
    for (int k = 0; k < 7; k++) qc *= qc;
    g_qC[i] = qc;
}

// ---------------------------------------------------------------------------
// Kernel A: zero-init local recurrence per chunk -> end states to g_state
// grid: (D/256, NCHUNK, B), block: 256 (one thread per d)
// Double-buffered prefetch of U=8 x values keeps MLP=8 per thread.
// ---------------------------------------------------------------------------
__global__ __launch_bounds__(256) void scanA(const float* __restrict__ x) {
    const int d = blockIdx.x * 256 + threadIdx.x;
    const int j = blockIdx.y;
    const int b = blockIdx.z;

    const u64* q2 = reinterpret_cast<const u64*>(g_q) + d * 8;
    u64 q[8], s[8];
    #pragma unroll
    for (int k = 0; k < 8; k++) { q[k] = q2[k]; s[k] = 0ull; }

    const float* p = x + (j * CHUNK) * BD + b * D_ + d;
    float xb[U];
    #pragma unroll
    for (int k = 0; k < U; k++) xb[k] = __ldg(p + k * BD);
    p += U * BD;

    #pragma unroll 1
    for (int i = 0; i < CHUNK / U - 1; i++) {
        float xn[U];
        #pragma unroll
        for (int k = 0; k < U; k++) xn[k] = __ldg(p + k * BD);   // next tile in flight
        p += U * BD;
        #pragma unroll
        for (int t = 0; t < U; t++) {
            u64 x2 = pack2(xb[t], xb[t]);
            #pragma unroll
            for (int k = 0; k < 8; k++) s[k] = fma2(q[k], s[k], x2);
        }
        #pragma unroll
        for (int k = 0; k < U; k++) xb[k] = xn[k];
    }
    // final tile (no further prefetch)
    #pragma unroll
    for (int t = 0; t < U; t++) {
        u64 x2 = pack2(xb[t], xb[t]);
        #pragma unroll
        for (int k = 0; k < 8; k++) s[k] = fma2(q[k], s[k], x2);
    }

    u64* st = reinterpret_cast<u64*>(g_state)
            + (unsigned)j * (BDN / 2) + (unsigned)b * (DN / 2) + d * 8;
    #pragma unroll
    for (int k = 0; k < 8; k++) st[k] = s[k];
}

// ---------------------------------------------------------------------------
// Kernel B: sequential scan across the 32 chunks per (b,d,n), in place:
// g_state[j] becomes the CARRY-IN state for chunk j.
// ---------------------------------------------------------------------------
__global__ void scanB() {
    int t = blockIdx.x * blockDim.x + threadIdx.x;   // 0..BDN-1
    float qc = g_qC[t & (DN - 1)];
    float carry = 0.0f;
    #pragma unroll
    for (int j = 0; j < NCHUNK; j++) {
        float e = g_state[j * BDN + t];
        g_state[j * BDN + t] = carry;                // carry-in for chunk j
        carry = fmaf(qc, carry, e);                  // state after chunk j
    }
}

// ---------------------------------------------------------------------------
// Kernel C: full recurrence from carry-in + projection + residual + ReLU
// grid: (D/256, NCHUNK, B), block: 256. Same U=8 prefetch pipeline.
// ---------------------------------------------------------------------------
__global__ __launch_bounds__(256) void scanC(const float* __restrict__ x,
                                             const float* __restrict__ rw,
                                             float* __restrict__ out) {
    const int d = blockIdx.x * 256 + threadIdx.x;
    const int j = blockIdx.y;
    const int b = blockIdx.z;

    const u64* q2 = reinterpret_cast<const u64*>(g_q) + d * 8;
    const u64* c2 = reinterpret_cast<const u64*>(g_c) + d * 8;
    const u64* st = reinterpret_cast<const u64*>(g_state)
                  + (unsigned)j * (BDN / 2) + (unsigned)b * (DN / 2) + d * 8;

    u64 q[8], c[8], s[8];
    #pragma unroll
    for (int k = 0; k < 8; k++) { q[k] = q2[k]; c[k] = c2[k]; s[k] = st[k]; }
    const float w = __ldg(rw + d);

    const int base0 = (j * CHUNK) * BD + b * D_ + d;
    const float* p = x + base0;
    float*       o = out + base0;

    float xb[U];
    #pragma unroll
    for (int k = 0; k < U; k++) xb[k] = __ldg(p + k * BD);
    p += U * BD;

    #pragma unroll 1
    for (int i = 0; i < CHUNK / U; i++) {
        float xn[U];
        if (i < CHUNK / U - 1) {
            #pragma unroll
            for (int k = 0; k < U; k++) xn[k] = __ldg(p + k * BD);  // next tile in flight
            p += U * BD;
        }
        #pragma unroll
        for (int t = 0; t < U; t++) {
            float xv = xb[t];
            u64 x2 = pack2(xv, xv);
            // state update: 8 independent fma2 chains
            #pragma unroll
            for (int k = 0; k < 8; k++) s[k] = fma2(q[k], s[k], x2);
            // projection reduce: 2 accumulators
            u64 a0 = 0ull, a1 = 0ull;
            #pragma unroll
            for (int k = 0; k < 4; k++) {
                a0 = fma2(c[k],     s[k],     a0);
                a1 = fma2(c[k + 4], s[k + 4], a1);
            }
            u64 a = add2(a0, a1);
            float lo, hi;
            unpack2(a, lo, hi);
            float r = fmaf(w, xv, lo + hi);          // + residual
            o[t * BD] = fmaxf(r, 0.0f);              // ReLU
        }
        o += U * BD;
        if (i < CHUNK / U - 1) {
            #pragma unroll
            for (int k = 0; k < U; k++) xb[k] = xn[k];
        }
    }
}

// ---------------------------------------------------------------------------
extern "C" void kernel_launch(void* const* d_in, const int* in_sizes, int n_in,
                              void* d_out, int out_size) {
    const float* x    = (const float*)d_in[0];  // (L,B,D)
    const float* damp = (const float*)d_in[1];  // (D,N,1)
    const float* dec  = (const float*)d_in[2];  // (D,N,1)
    const float* ema  = (const float*)d_in[3];  // (D,N,1)
    const float* proj = (const float*)d_in[4];  // (D,N)
    const float* rw   = (const float*)d_in[5];  // (D,)
    float* out = (float*)d_out;                 // (L,B,D)

    param_kernel<<<DN / 256, 256>>>(damp, dec, ema, proj);
    scanA<<<dim3(D_ / 256, NCHUNK, B_), 256>>>(x);
    scanB<<<BDN / 256, 256>>>();
    scanC<<<dim3(D_ / 256, NCHUNK, B_), 256>>>(x, rw, out);
}

// round 16
// speedup vs baseline: 1.0050x; 1.0008x over previous
#include <cuda_runtime.h>

// Shapes fixed by the problem: L=4096, B=8, D=1024, N=16
#define L_      4096
#define B_      8
#define D_      1024
#define N_      16
#define CHUNK   128
#define NCHUNK  (L_ / CHUNK)      // 32
#define BD      (B_ * D_)         // 8192
#define DN      (D_ * N_)         // 16384
#define BDN     (B_ * DN)         // 131072
#define U       8                 // prefetch depth (MLP)

// Scratch (device-global arrays: the sanctioned no-alloc workaround)
__device__ float g_q [DN];                    // q[d,n]
__device__ float g_c [DN];                    // c[d,n] = sig(damp)*ema*proj*scaling
__device__ float g_qC[DN];                    // q^CHUNK
__device__ float g_state[NCHUNK * BDN];       // 16 MB chunk states / carry-ins

typedef unsigned long long u64;

__device__ __forceinline__ u64 fma2(u64 a, u64 b, u64 c) {
    u64 d;
    asm("fma.rn.f32x2 %0, %1, %2, %3;" : "=l"(d) : "l"(a), "l"(b), "l"(c));
    return d;
}
__device__ __forceinline__ u64 add2(u64 a, u64 b) {
    u64 d;
    asm("add.rn.f32x2 %0, %1, %2;" : "=l"(d) : "l"(a), "l"(b));
    return d;
}
__device__ __forceinline__ u64 pack2(float a, float b) {
    u64 r;
    asm("mov.b64 %0, {%1, %2};" : "=l"(r) : "f"(a), "f"(b));
    return r;
}
__device__ __forceinline__ void unpack2(u64 v, float& a, float& b) {
    asm("mov.b64 {%0, %1}, %2;" : "=f"(a), "=f"(b) : "l"(v));
}

// ---------------------------------------------------------------------------
// Kernel P: per-(d,n) parameter precompute
// ---------------------------------------------------------------------------
__global__ void param_kernel(const float* __restrict__ damp,
                             const float* __restrict__ decay,
                             const float* __restrict__ ema,
                             const float* __restrict__ proj) {
    int i = blockIdx.x * blockDim.x + threadIdx.x;
    if (i >= DN) return;
    float p  = 1.0f / (1.0f + expf(-damp[i]));
    float sd = 1.0f / (1.0f + expf(-decay[i]));
    float q  = 1.0f - p * sd;                    // q in (0,1)
    g_q[i] = q;
    g_c[i] = p * ema[i] * proj[i] * 0.25f;       // scaling = (1/16)^0.5
    float qc = q;                                 // q^128 via 7 squarings
    #pragma unroll
    for (int k = 0; k < 7; k++) qc *= qc;
    g_qC[i] = qc;
}

// ---------------------------------------------------------------------------
// Kernel A: zero-init local recurrence per chunk -> end states to g_state
// grid: (D/256, NCHUNK, B), block: 256 (one thread per d)
// Double-buffered prefetch of U=8 x values keeps MLP=8 per thread.
// ---------------------------------------------------------------------------
__global__ __launch_bounds__(256) void scanA(const float* __restrict__ x) {
    const int d = blockIdx.x * 256 + threadIdx.x;
    const int j = blockIdx.y;
    const int b = blockIdx.z;

    const u64* q2 = reinterpret_cast<const u64*>(g_q) + d * 8;
    u64 q[8], s[8];
    #pragma unroll
    for (int k = 0; k < 8; k++) { q[k] = q2[k]; s[k] = 0ull; }

    const float* p = x + (j * CHUNK) * BD + b * D_ + d;
    float xb[U];
    #pragma unroll
    for (int k = 0; k < U; k++) xb[k] = __ldg(p + k * BD);
    p += U * BD;

    #pragma unroll 1
    for (int i = 0; i < CHUNK / U - 1; i++) {
        float xn[U];
        #pragma unroll
        for (int k = 0; k < U; k++) xn[k] = __ldg(p + k * BD);   // next tile in flight
        p += U * BD;
        #pragma unroll
        for (int t = 0; t < U; t++) {
            u64 x2 = pack2(xb[t], xb[t]);
            #pragma unroll
            for (int k = 0; k < 8; k++) s[k] = fma2(q[k], s[k], x2);
        }
        #pragma unroll
        for (int k = 0; k < U; k++) xb[k] = xn[k];
    }
    // final tile (no further prefetch)
    #pragma unroll
    for (int t = 0; t < U; t++) {
        u64 x2 = pack2(xb[t], xb[t]);
        #pragma unroll
        for (int k = 0; k < 8; k++) s[k] = fma2(q[k], s[k], x2);
    }

    u64* st = reinterpret_cast<u64*>(g_state)
            + (unsigned)j * (BDN / 2) + (unsigned)b * (DN / 2) + d * 8;
    #pragma unroll
    for (int k = 0; k < 8; k++) st[k] = s[k];
}

// ---------------------------------------------------------------------------
// Kernel B: sequential scan across the 32 chunks per (b,d,n), in place:
// g_state[j] becomes the CARRY-IN state for chunk j.
// ---------------------------------------------------------------------------
__global__ void scanB() {
    int t = blockIdx.x * blockDim.x + threadIdx.x;   // 0..BDN-1
    float qc = g_qC[t & (DN - 1)];
    float carry = 0.0f;
    #pragma unroll
    for (int j = 0; j < NCHUNK; j++) {
        float e = g_state[j * BDN + t];
        g_state[j * BDN + t] = carry;                // carry-in for chunk j
        carry = fmaf(qc, carry, e);                  // state after chunk j
    }
}

// ---------------------------------------------------------------------------
// Kernel C: full recurrence from carry-in + projection + residual + ReLU
// grid: (D/256, NCHUNK, B), block: 256. Same U=8 prefetch pipeline.
// ---------------------------------------------------------------------------
__global__ __launch_bounds__(256) void scanC(const float* __restrict__ x,
                                             const float* __restrict__ rw,
                                             float* __restrict__ out) {
    const int d = blockIdx.x * 256 + threadIdx.x;
    const int j = blockIdx.y;
    const int b = blockIdx.z;

    const u64* q2 = reinterpret_cast<const u64*>(g_q) + d * 8;
    const u64* c2 = reinterpret_cast<const u64*>(g_c) + d * 8;
    const u64* st = reinterpret_cast<const u64*>(g_state)
                  + (unsigned)j * (BDN / 2) + (unsigned)b * (DN / 2) + d * 8;

    u64 q[8], c[8], s[8];
    #pragma unroll
    for (int k = 0; k < 8; k++) { q[k] = q2[k]; c[k] = c2[k]; s[k] = st[k]; }
    const float w = __ldg(rw + d);

    const int base0 = (j * CHUNK) * BD + b * D_ + d;
    const float* p = x + base0;
    float*       o = out + base0;

    float xb[U];
    #pragma unroll
    for (int k = 0; k < U; k++) xb[k] = __ldg(p + k * BD);
    p += U * BD;

    #pragma unroll 1
    for (int i = 0; i < CHUNK / U; i++) {
        float xn[U];
        if (i < CHUNK / U - 1) {
            #pragma unroll
            for (int k = 0; k < U; k++) xn[k] = __ldg(p + k * BD);  // next tile in flight
            p += U * BD;
        }
        #pragma unroll
        for (int t = 0; t < U; t++) {
            float xv = xb[t];
            u64 x2 = pack2(xv, xv);
            // state update: 8 independent fma2 chains
            #pragma unroll
            for (int k = 0; k < 8; k++) s[k] = fma2(q[k], s[k], x2);
            // projection reduce: 2 accumulators
            u64 a0 = 0ull, a1 = 0ull;
            #pragma unroll
            for (int k = 0; k < 4; k++) {
                a0 = fma2(c[k],     s[k],     a0);
                a1 = fma2(c[k + 4], s[k + 4], a1);
            }
            u64 a = add2(a0, a1);
            float lo, hi;
            unpack2(a, lo, hi);
            float r = fmaf(w, xv, lo + hi);          // + residual
            o[t * BD] = fmaxf(r, 0.0f);              // ReLU
        }
        o += U * BD;
        if (i < CHUNK / U - 1) {
            #pragma unroll
            for (int k = 0; k < U; k++) xb[k] = xn[k];
        }
    }
}

// ---------------------------------------------------------------------------
extern "C" void kernel_launch(void* const* d_in, const int* in_sizes, int n_in,
                              void* d_out, int out_size) {
    const float* x    = (const float*)d_in[0];  // (L,B,D)
    const float* damp = (const float*)d_in[1];  // (D,N,1)
    const float* dec  = (const float*)d_in[2];  // (D,N,1)
    const float* ema  = (const float*)d_in[3];  // (D,N,1)
    const float* proj = (const float*)d_in[4];  // (D,N)
    const float* rw   = (const float*)d_in[5];  // (D,)
    float* out = (float*)d_out;                 // (L,B,D)

    param_kernel<<<DN / 256, 256>>>(damp, dec, ema, proj);
    scanA<<<dim3(D_ / 256, NCHUNK, B_), 256>>>(x);
    scanB<<<BDN / 256, 256>>>();
    scanC<<<dim3(D_ / 256, NCHUNK, B_), 256>>>(x, rw, out);
}